// round 11
// baseline (speedup 1.0000x reference)
#include <cuda_runtime.h>
#include <cstddef>

#define NBLK   148
#define NTHR   1024
#define NWARPS (NBLK * 32)       // 4736
#define NPAIRS 65536             // 131072 rows / 2
#define MDIM   450

// L2-resident split of dec_W2 (pairs of rows; 3600B/pair)
#define PR_RES   26624           // 26624*3600 = 95,846,400 B kept evict-normal
#define PF_LINES 748800u         // exact resident 128B-line count
#define PF_PER_PHASE 187200u     // PF_LINES / 4 phases
#define PF_THREADS 136192u       // 133 blocks * 1024 threads

// Scratch (device globals; no allocation)
__device__ __align__(16) float g_Fpart[128 * 128];
__device__ __align__(16) float g_feat[452];
__device__ __align__(16) float g_h[452];
__device__ __align__(16) float g_feat2[452];
__device__ __align__(16) float g_h2[452];

// Flag-array grid barrier: one flag per block, no same-address atomics.
// Flags persist across graph replays; every launch advances each flag by
// exactly NBARS, and targets are relative to the value read at kernel entry.
__device__ volatile unsigned g_flags[NBLK];   // zero-initialized

__device__ __forceinline__ void grid_bar(unsigned target)
{
    __syncthreads();
    if (threadIdx.x == 0) {
        __threadfence();                      // publish this block's stores
        g_flags[blockIdx.x] = target;
    }
    if (threadIdx.x < NBLK) {
        while ((int)(g_flags[threadIdx.x] - target) < 0) { }
        __threadfence();                      // acquire
    }
    __syncthreads();
}

// Bounded L2 prefetch of the resident region only. phase in [0,4).
// Max byte touched = (PF_LINES-1)*128+127 < 95.9MB << 236MB allocation.
__device__ __forceinline__ void pf_resident(const float* dW2, int phase)
{
    const unsigned base = phase * PF_PER_PHASE;
    const unsigned hi   = base + PF_PER_PHASE;           // <= PF_LINES
    const unsigned my   = (blockIdx.x - 15) * NTHR + threadIdx.x;
    const char* p = (const char*)dW2;
    #pragma unroll
    for (unsigned k = 0; k < 2; ++k) {
        unsigned line = base + my + k * PF_THREADS;
        if (line < hi)
            asm volatile("prefetch.global.L2 [%0];" :: "l"(p + (size_t)line * 128));
    }
}

// Warp-per-row 450x450 matvec: vout = [relu](W @ vin + b). Blocks 0..14.
__device__ __forceinline__ void mv450_stage(const float* __restrict__ W,
                                            const float* __restrict__ b,
                                            const float* __restrict__ vin_g,
                                            float* __restrict__ vout_g,
                                            bool do_relu, float* sh)
{
    const int tid = threadIdx.x;
    if (tid < MDIM) sh[tid] = __ldcg(vin_g + tid);
    __syncthreads();

    const int wid  = tid >> 5;
    const int lane = tid & 31;
    const int row  = blockIdx.x * 32 + wid;
    if (row < MDIM) {
        const float2* wr = reinterpret_cast<const float2*>(W + (size_t)row * MDIM);
        const float2* sv = reinterpret_cast<const float2*>(sh);
        float acc = 0.f;
        #pragma unroll
        for (int j = 0; j < 7; ++j) {
            const float2 w = __ldg(wr + lane + 32 * j);
            const float2 v = sv[lane + 32 * j];
            acc += w.x * v.x + w.y * v.y;
        }
        if (lane == 0) {
            const float2 w = __ldg(wr + 224);
            const float2 v = sv[224];
            acc += w.x * v.x + w.y * v.y;
        }
        #pragma unroll
        for (int o = 16; o; o >>= 1) acc += __shfl_xor_sync(0xFFFFFFFFu, acc, o);
        if (lane == 0) {
            float r = acc + __ldg(b + row);
            vout_g[row] = do_relu ? fmaxf(r, 0.f) : r;
        }
    }
}

// One dec row-pair dot: 3600B contiguous segment, 225 float4.
// STREAM=false -> __ldg (evict-normal, stays in L2); true -> __ldcs.
template<bool STREAM>
__device__ __forceinline__ void dec_pair(const float4* __restrict__ wr,
                                         const float4* __restrict__ VV,
                                         int lane, float& acc0, float& acc1)
{
    float4 w0 = STREAM ? __ldcs(wr + lane)       : __ldg(wr + lane);
    float4 w1 = STREAM ? __ldcs(wr + lane + 32)  : __ldg(wr + lane + 32);
    float4 w2 = STREAM ? __ldcs(wr + lane + 64)  : __ldg(wr + lane + 64);
    float4 w3 = STREAM ? __ldcs(wr + lane + 96)  : __ldg(wr + lane + 96);
    float4 w4 = STREAM ? __ldcs(wr + lane + 128) : __ldg(wr + lane + 128);
    float4 w5 = STREAM ? __ldcs(wr + lane + 160) : __ldg(wr + lane + 160);
    float4 w6 = STREAM ? __ldcs(wr + lane + 192) : __ldg(wr + lane + 192);
    float4 wt;
    if (lane == 0) wt = STREAM ? __ldcs(wr + 224) : __ldg(wr + 224);

    float4 v = VV[lane];
    acc0 = w0.x*v.x + w0.y*v.y + w0.z*v.z + w0.w*v.w;
    v = VV[lane + 32];
    acc0 += w1.x*v.x + w1.y*v.y + w1.z*v.z + w1.w*v.w;
    v = VV[lane + 64];
    acc0 += w2.x*v.x + w2.y*v.y + w2.z*v.z + w2.w*v.w;
    v = VV[lane + 128];
    acc1 = w4.x*v.x + w4.y*v.y + w4.z*v.z + w4.w*v.w;
    v = VV[lane + 160];
    acc1 += w5.x*v.x + w5.y*v.y + w5.z*v.z + w5.w*v.w;
    v = VV[lane + 192];
    acc1 += w6.x*v.x + w6.y*v.y + w6.z*v.z + w6.w*v.w;
    // straddle: float4 idx lane+96 covers elements 448..451 at lane 16
    v = VV[lane + 96];
    {
        const float dlo = w3.x*v.x + w3.y*v.y;
        const float dhi = w3.z*v.z + w3.w*v.w;
        acc0 += (lane < 16) ? (dlo + dhi) : ((lane == 16) ? dlo : 0.f);
        acc1 += (lane > 16) ? (dlo + dhi) : ((lane == 16) ? dhi : 0.f);
    }
    if (lane == 0) {
        v = VV[224];
        acc1 += wt.x*v.x + wt.y*v.y + wt.z*v.z + wt.w*v.w;
    }
}

__global__ void __launch_bounds__(NTHR, 1)
fused_kernel(const float* __restrict__ x,   const float* __restrict__ TwE,
             const float* __restrict__ PE,  const float* __restrict__ CE,
             const float* __restrict__ mE,
             const float* __restrict__ eW1, const float* __restrict__ eb1,
             const float* __restrict__ eW2, const float* __restrict__ eb2,
             const float* __restrict__ dW1, const float* __restrict__ db1,
             const float* __restrict__ dW2, const float* __restrict__ db2,
             float* __restrict__ out, int xoff)
{
    __shared__ float sh[10240];            // 40KB, reused per stage
    const int tid  = threadIdx.x;
    const int wid  = tid >> 5;
    const int lane = tid & 31;
    const int blk  = blockIdx.x;

    // barrier base: this block's own flag (only this block writes it)
    const unsigned bar0 = g_flags[blk];

    // ===== Stage 1: f partials. 128 blocks x 8 tp-rows each. =====
    if (blk < 128) {
        float* sx = sh;                    // [8][128] x rows
        float* sp = sh + 1024;             // [8 chunks][8 rows][128 i]
        sx[tid] = x[xoff + blk * 1024 + tid];
        __syncthreads();

        const int pr = wid & 3;
        const int ch = wid >> 2;
        const int i0 = lane * 4;
        const int r0 = pr * 2, r1 = r0 + 1;
        float4 a0 = {0,0,0,0}, a1 = {0,0,0,0};
        const int cb = ch * 16;
        #pragma unroll
        for (int cc = 0; cc < 16; ++cc) {
            const int c = cb + cc;
            const float4 ce = *reinterpret_cast<const float4*>(CE + c * 128 + i0);
            const float x0 = sx[r0 * 128 + c];
            const float x1 = sx[r1 * 128 + c];
            a0.x += x0 * ce.x; a0.y += x0 * ce.y; a0.z += x0 * ce.z; a0.w += x0 * ce.w;
            a1.x += x1 * ce.x; a1.y += x1 * ce.y; a1.z += x1 * ce.z; a1.w += x1 * ce.w;
        }
        *reinterpret_cast<float4*>(sp + (ch * 8 + r0) * 128 + i0) = a0;
        *reinterpret_cast<float4*>(sp + (ch * 8 + r1) * 128 + i0) = a1;
        __syncthreads();

        const int row = tid >> 7;          // 0..7
        const int i   = tid & 127;
        float s = 0.f;
        #pragma unroll
        for (int c2 = 0; c2 < 8; ++c2) s += sp[(c2 * 8 + row) * 128 + i];
        const int gr = blk * 8 + row;
        s *= __ldg(PE + (gr & 255) * 128 + i) * __ldg(TwE + (gr >> 8) * 128 + i);
        __syncthreads();
        sh[tid] = s;
        __syncthreads();
        if (tid < 128) {
            float t2 = 0.f;
            #pragma unroll
            for (int r = 0; r < 8; ++r) t2 += sh[r * 128 + tid];
            g_Fpart[blk * 128 + tid] = t2;
        }
    }
    grid_bar(bar0 + 1);

    // ===== Stage 2: feat = mE @ f (blocks 0..14); others prefetch phase 0 =====
    if (blk < 15) {
        float* tmp = sh + 1024;
        {
            const int grp = tid >> 7;      // 0..7, each sums 16 partials
            const int i   = tid & 127;
            float s = 0.f;
            #pragma unroll
            for (int b = 0; b < 16; ++b)
                s += __ldcg(&g_Fpart[(grp * 16 + b) * 128 + i]);
            tmp[grp * 128 + i] = s;
        }
        __syncthreads();
        if (tid < 128) {
            float s = 0.f;
            #pragma unroll
            for (int g = 0; g < 8; ++g) s += tmp[g * 128 + tid];
            sh[tid] = s;
        }
        __syncthreads();
        const int row = blk * 32 + wid;
        if (row < MDIM) {
            const float* r = mE + row * 128;
            float acc = __ldg(r + lane)       * sh[lane]
                      + __ldg(r + lane + 32)  * sh[lane + 32]
                      + __ldg(r + lane + 64)  * sh[lane + 64]
                      + __ldg(r + lane + 96)  * sh[lane + 96];
            #pragma unroll
            for (int o = 16; o; o >>= 1) acc += __shfl_xor_sync(0xFFFFFFFFu, acc, o);
            if (lane == 0) g_feat[row] = acc;
        }
    } else {
        pf_resident(dW2, 0);
    }
    grid_bar(bar0 + 2);

    // ===== Stages 3..5: 450x450 chain (blocks 0..14); others prefetch =====
    if (blk < 15) mv450_stage(eW1, eb1, g_feat, g_h, true, sh);
    else pf_resident(dW2, 1);
    grid_bar(bar0 + 3);
    if (blk < 15) mv450_stage(eW2, eb2, g_h, g_feat2, false, sh);
    else pf_resident(dW2, 2);
    grid_bar(bar0 + 4);
    if (blk < 15) mv450_stage(dW1, db1, g_feat2, g_h2, true, sh);
    else pf_resident(dW2, 3);
    grid_bar(bar0 + 5);

    // ===== Stage 6: out = dec_W2 @ h2 + db2 (131072 x 450) =====
    {
        for (int i = tid; i < 900; i += NTHR)
            sh[i] = __ldcg(&g_h2[(i < 450) ? i : (i - 450)]);
        __syncthreads();
        const float4* VV = reinterpret_cast<const float4*>(sh);
        const int gw = blk * 32 + wid;
        const bool lo16 = (lane < 16);

        int pr = gw;
        // resident half: evict-normal loads -> stays in L2 across graph replays
        for (; pr < PR_RES; pr += NWARPS) {
            const float4* wr = reinterpret_cast<const float4*>(dW2 + (size_t)pr * 900);
            float acc0, acc1;
            dec_pair<false>(wr, VV, lane, acc0, acc1);
            // 5-shuffle dual reduction: lane0 <- sum(acc0), lane16 <- sum(acc1)
            float z = lo16 ? acc0 : acc1;
            z += __shfl_xor_sync(0xFFFFFFFFu, lo16 ? acc1 : acc0, 16);
            #pragma unroll
            for (int o = 8; o; o >>= 1) z += __shfl_xor_sync(0xFFFFFFFFu, z, o);
            if (lane == 0)  out[2 * pr]     = z + __ldg(db2 + 2 * pr);
            if (lane == 16) out[2 * pr + 1] = z + __ldg(db2 + 2 * pr + 1);
        }
        // streaming half: evict-first, doesn't displace the resident half
        for (; pr < NPAIRS; pr += NWARPS) {
            const float4* wr = reinterpret_cast<const float4*>(dW2 + (size_t)pr * 900);
            float acc0, acc1;
            dec_pair<true>(wr, VV, lane, acc0, acc1);
            float z = lo16 ? acc0 : acc1;
            z += __shfl_xor_sync(0xFFFFFFFFu, lo16 ? acc1 : acc0, 16);
            #pragma unroll
            for (int o = 8; o; o >>= 1) z += __shfl_xor_sync(0xFFFFFFFFu, z, o);
            if (lane == 0)  out[2 * pr]     = z + __ldg(db2 + 2 * pr);
            if (lane == 16) out[2 * pr + 1] = z + __ldg(db2 + 2 * pr + 1);
        }
    }
}

// ---------------------------------------------------------------------------
// Inputs: x, t, TwE, PE, CE, mE, ext_W1, ext_b1, ext_W2, ext_b2,
//         dec_W1, dec_b1, dec_W2, dec_b2
// ---------------------------------------------------------------------------
extern "C" void kernel_launch(void* const* d_in, const int* in_sizes, int n_in,
                              void* d_out, int out_size)
{
    const float* x   = (const float*)d_in[0];
    const float* TwE = (const float*)d_in[2];
    const float* PE  = (const float*)d_in[3];
    const float* CE  = (const float*)d_in[4];
    const float* mE  = (const float*)d_in[5];
    const float* eW1 = (const float*)d_in[6];
    const float* eb1 = (const float*)d_in[7];
    const float* eW2 = (const float*)d_in[8];
    const float* eb2 = (const float*)d_in[9];
    const float* dW1 = (const float*)d_in[10];
    const float* db1 = (const float*)d_in[11];
    const float* dW2 = (const float*)d_in[12];
    const float* db2 = (const float*)d_in[13];
    float* out = (float*)d_out;

    const int xoff = in_sizes[0] - 4 * 256 * 128;

    fused_kernel<<<NBLK, NTHR>>>(x, TwE, PE, CE, mE,
                                 eW1, eb1, eW2, eb2,
                                 dW1, db1, dW2, db2,
                                 out, xoff);
    (void)n_in; (void)out_size;
}

// round 12
// speedup vs baseline: 1.3187x; 1.3187x over previous
#include <cuda_runtime.h>
#include <cstddef>

#define NBLK   148
#define NTHR   1024
#define NWARPS (NBLK * 32)       // 4736
#define NPAIRS 65536             // 131072 rows / 2
#define MDIM   450

// L2-resident split of dec_W2 (pairs of rows; 3600B/pair)
#define PR_RES   26624           // 26624*3600 = 95,846,400 B kept evict-normal
#define PF_LINES 748800u         // exact resident 128B-line count (<< 236MB alloc)

// Scratch (device globals; no allocation)
__device__ __align__(16) float g_Fpart[128 * 128];
__device__ __align__(16) float g_feat[452];
__device__ __align__(16) float g_h[452];
__device__ __align__(16) float g_feat2[452];
__device__ __align__(16) float g_h2[452];

// Sync state (monotonic generations -> safe across sequential graph replays)
__device__ unsigned g_count = 0;              // full 148-block barrier
__device__ volatile unsigned g_gen = 0;
__device__ unsigned g_ccount = 0;             // 15-block chain barrier
__device__ volatile unsigned g_cgen = 0;
__device__ unsigned g_hcount = 0;             // h2-ready signal (15 arrivals)
__device__ volatile unsigned g_h2gen = 0;

// Full-grid barrier (proven R2/R8 pattern: 1 atomic + 1 spinner per block)
__device__ __forceinline__ void grid_bar()
{
    __syncthreads();
    if (threadIdx.x == 0) {
        const unsigned gen = g_gen;
        __threadfence();
        if (atomicAdd(&g_count, 1u) == (unsigned)NBLK - 1u) {
            atomicExch(&g_count, 0u);
            __threadfence();
            g_gen = gen + 1u;
        } else {
            while (g_gen == gen) { }
            __threadfence();
        }
    }
    __syncthreads();
}

// 15-block chain barrier (blocks 0..14 only)
__device__ __forceinline__ void chain_bar()
{
    __syncthreads();
    if (threadIdx.x == 0) {
        const unsigned gen = g_cgen;
        __threadfence();
        if (atomicAdd(&g_ccount, 1u) == 14u) {
            atomicExch(&g_ccount, 0u);
            __threadfence();
            g_cgen = gen + 1u;
        } else {
            while (g_cgen == gen) { }
            __threadfence();
        }
    }
    __syncthreads();
}

// Bounded prefetch of the resident dec_W2 region: blocks 15..147, 5632 lines each.
// Max byte touched = (PF_LINES-1)*128 + 127 < 95.9MB << 236MB allocation.
__device__ __forceinline__ void pf_resident_all(const float* dW2)
{
    const unsigned start = (blockIdx.x - 15) * 5632u;
    const unsigned hi0   = start + 5632u;
    const unsigned hi    = (hi0 < PF_LINES) ? hi0 : PF_LINES;
    const char* p = (const char*)dW2;
    #pragma unroll
    for (unsigned k = 0; k < 6; ++k) {
        const unsigned line = start + threadIdx.x + k * 1024u;
        if (line < hi)
            asm volatile("prefetch.global.L2 [%0];" :: "l"(p + (size_t)line * 128));
    }
}

// Prefetch chain weights during stage 1 (blocks 128..147, 20480 threads).
// Exact full-line bounds: 450x450 f32 = 810000B -> lines 0..6327 fully inside.
// mE: 450x128 f32 = 230400B = 1800 lines. db2: 131072 f32 = 4096 lines.
__device__ __forceinline__ void pf_chain(const float* eW1, const float* eW2,
                                         const float* dW1, const float* mE,
                                         const float* db2)
{
    const unsigned my = (blockIdx.x - 128) * 1024u + threadIdx.x; // 0..20479
    if (my < 6328u) {
        asm volatile("prefetch.global.L2 [%0];" :: "l"((const char*)eW1 + (size_t)my * 128));
        asm volatile("prefetch.global.L2 [%0];" :: "l"((const char*)eW2 + (size_t)my * 128));
        asm volatile("prefetch.global.L2 [%0];" :: "l"((const char*)dW1 + (size_t)my * 128));
    }
    if (my < 1800u)
        asm volatile("prefetch.global.L2 [%0];" :: "l"((const char*)mE + (size_t)my * 128));
    if (my < 4096u)
        asm volatile("prefetch.global.L2 [%0];" :: "l"((const char*)db2 + (size_t)my * 128));
}

// Warp-per-row 450x450 matvec: vout = [relu](W @ vin + b). Blocks 0..14.
__device__ __forceinline__ void mv450_stage(const float* __restrict__ W,
                                            const float* __restrict__ b,
                                            const float* __restrict__ vin_g,
                                            float* __restrict__ vout_g,
                                            bool do_relu, float* sh)
{
    const int tid = threadIdx.x;
    if (tid < MDIM) sh[tid] = __ldcg(vin_g + tid);
    __syncthreads();

    const int wid  = tid >> 5;
    const int lane = tid & 31;
    const int row  = blockIdx.x * 32 + wid;
    if (row < MDIM) {
        const float2* wr = reinterpret_cast<const float2*>(W + (size_t)row * MDIM);
        const float2* sv = reinterpret_cast<const float2*>(sh);
        float acc = 0.f;
        #pragma unroll
        for (int j = 0; j < 7; ++j) {
            const float2 w = __ldg(wr + lane + 32 * j);
            const float2 v = sv[lane + 32 * j];
            acc += w.x * v.x + w.y * v.y;
        }
        if (lane == 0) {
            const float2 w = __ldg(wr + 224);
            const float2 v = sv[224];
            acc += w.x * v.x + w.y * v.y;
        }
        #pragma unroll
        for (int o = 16; o; o >>= 1) acc += __shfl_xor_sync(0xFFFFFFFFu, acc, o);
        if (lane == 0) {
            float r = acc + __ldg(b + row);
            vout_g[row] = do_relu ? fmaxf(r, 0.f) : r;
        }
    }
}

// One dec row-pair dot: 3600B contiguous segment, 225 float4.
template<bool STREAM>
__device__ __forceinline__ void dec_pair(const float4* __restrict__ wr,
                                         const float4* __restrict__ VV,
                                         int lane, float& acc0, float& acc1)
{
    float4 w0 = STREAM ? __ldcs(wr + lane)       : __ldg(wr + lane);
    float4 w1 = STREAM ? __ldcs(wr + lane + 32)  : __ldg(wr + lane + 32);
    float4 w2 = STREAM ? __ldcs(wr + lane + 64)  : __ldg(wr + lane + 64);
    float4 w3 = STREAM ? __ldcs(wr + lane + 96)  : __ldg(wr + lane + 96);
    float4 w4 = STREAM ? __ldcs(wr + lane + 128) : __ldg(wr + lane + 128);
    float4 w5 = STREAM ? __ldcs(wr + lane + 160) : __ldg(wr + lane + 160);
    float4 w6 = STREAM ? __ldcs(wr + lane + 192) : __ldg(wr + lane + 192);
    float4 wt;
    if (lane == 0) wt = STREAM ? __ldcs(wr + 224) : __ldg(wr + 224);

    float4 v = VV[lane];
    acc0 = w0.x*v.x + w0.y*v.y + w0.z*v.z + w0.w*v.w;
    v = VV[lane + 32];
    acc0 += w1.x*v.x + w1.y*v.y + w1.z*v.z + w1.w*v.w;
    v = VV[lane + 64];
    acc0 += w2.x*v.x + w2.y*v.y + w2.z*v.z + w2.w*v.w;
    v = VV[lane + 128];
    acc1 = w4.x*v.x + w4.y*v.y + w4.z*v.z + w4.w*v.w;
    v = VV[lane + 160];
    acc1 += w5.x*v.x + w5.y*v.y + w5.z*v.z + w5.w*v.w;
    v = VV[lane + 192];
    acc1 += w6.x*v.x + w6.y*v.y + w6.z*v.z + w6.w*v.w;
    v = VV[lane + 96];                      // straddle at lane 16
    {
        const float dlo = w3.x*v.x + w3.y*v.y;
        const float dhi = w3.z*v.z + w3.w*v.w;
        acc0 += (lane < 16) ? (dlo + dhi) : ((lane == 16) ? dlo : 0.f);
        acc1 += (lane > 16) ? (dlo + dhi) : ((lane == 16) ? dhi : 0.f);
    }
    if (lane == 0) {
        v = VV[224];
        acc1 += wt.x*v.x + wt.y*v.y + wt.z*v.z + wt.w*v.w;
    }
}

__global__ void __launch_bounds__(NTHR, 1)
fused_kernel(const float* __restrict__ x,   const float* __restrict__ TwE,
             const float* __restrict__ PE,  const float* __restrict__ CE,
             const float* __restrict__ mE,
             const float* __restrict__ eW1, const float* __restrict__ eb1,
             const float* __restrict__ eW2, const float* __restrict__ eb2,
             const float* __restrict__ dW1, const float* __restrict__ db1,
             const float* __restrict__ dW2, const float* __restrict__ db2,
             float* __restrict__ out, int xoff)
{
    __shared__ float sh[10240];            // 40KB, reused per stage
    const int tid  = threadIdx.x;
    const int wid  = tid >> 5;
    const int lane = tid & 31;
    const int blk  = blockIdx.x;

    // capture h2 generation at entry (bump happens strictly after the full
    // barrier below, which this block participates in -> no race)
    const unsigned h2base = g_h2gen;

    // ===== Stage 1: f partials. Blocks 0..127; blocks 128..147 prefetch. =====
    if (blk < 128) {
        float* sx = sh;                    // [8][128] x rows
        float* sp = sh + 1024;             // [8 chunks][8 rows][128 i]
        sx[tid] = x[xoff + blk * 1024 + tid];
        __syncthreads();

        const int pr = wid & 3;
        const int ch = wid >> 2;
        const int i0 = lane * 4;
        const int r0 = pr * 2, r1 = r0 + 1;
        float4 a0 = {0,0,0,0}, a1 = {0,0,0,0};
        const int cb = ch * 16;
        #pragma unroll
        for (int cc = 0; cc < 16; ++cc) {
            const int c = cb + cc;
            const float4 ce = *reinterpret_cast<const float4*>(CE + c * 128 + i0);
            const float x0 = sx[r0 * 128 + c];
            const float x1 = sx[r1 * 128 + c];
            a0.x += x0 * ce.x; a0.y += x0 * ce.y; a0.z += x0 * ce.z; a0.w += x0 * ce.w;
            a1.x += x1 * ce.x; a1.y += x1 * ce.y; a1.z += x1 * ce.z; a1.w += x1 * ce.w;
        }
        *reinterpret_cast<float4*>(sp + (ch * 8 + r0) * 128 + i0) = a0;
        *reinterpret_cast<float4*>(sp + (ch * 8 + r1) * 128 + i0) = a1;
        __syncthreads();

        const int row = tid >> 7;          // 0..7
        const int i   = tid & 127;
        float s = 0.f;
        #pragma unroll
        for (int c2 = 0; c2 < 8; ++c2) s += sp[(c2 * 8 + row) * 128 + i];
        const int gr = blk * 8 + row;
        s *= __ldg(PE + (gr & 255) * 128 + i) * __ldg(TwE + (gr >> 8) * 128 + i);
        __syncthreads();
        sh[tid] = s;
        __syncthreads();
        if (tid < 128) {
            float t2 = 0.f;
            #pragma unroll
            for (int r = 0; r < 8; ++r) t2 += sh[r * 128 + tid];
            g_Fpart[blk * 128 + tid] = t2;
        }
    } else {
        pf_chain(eW1, eW2, dW1, mE, db2);
    }
    grid_bar();                            // the ONLY full-grid barrier

    if (blk < 15) {
        // ===== Stage 2: feat = mE @ f =====
        {
            float* tmp = sh + 1024;
            const int grp = tid >> 7;      // 0..7, each sums 16 partials
            const int i   = tid & 127;
            float s = 0.f;
            #pragma unroll
            for (int b = 0; b < 16; ++b)
                s += __ldcg(&g_Fpart[(grp * 16 + b) * 128 + i]);
            tmp[grp * 128 + i] = s;
            __syncthreads();
            if (tid < 128) {
                float s2 = 0.f;
                #pragma unroll
                for (int g = 0; g < 8; ++g) s2 += tmp[g * 128 + tid];
                sh[tid] = s2;
            }
            __syncthreads();
            const int row = blk * 32 + wid;
            if (row < MDIM) {
                const float* r = mE + row * 128;
                float acc = __ldg(r + lane)       * sh[lane]
                          + __ldg(r + lane + 32)  * sh[lane + 32]
                          + __ldg(r + lane + 64)  * sh[lane + 64]
                          + __ldg(r + lane + 96)  * sh[lane + 96];
                #pragma unroll
                for (int o = 16; o; o >>= 1) acc += __shfl_xor_sync(0xFFFFFFFFu, acc, o);
                if (lane == 0) g_feat[row] = acc;
            }
        }
        chain_bar();
        // ===== Stages 3..5 =====
        mv450_stage(eW1, eb1, g_feat,  g_h,     true,  sh);
        chain_bar();
        mv450_stage(eW2, eb2, g_h,     g_feat2, false, sh);
        chain_bar();
        mv450_stage(dW1, db1, g_feat2, g_h2,    true,  sh);
        // h2-ready signal (15th arrival bumps generation)
        __syncthreads();
        if (tid == 0) {
            __threadfence();
            if (atomicAdd(&g_hcount, 1u) == 14u) {
                atomicExch(&g_hcount, 0u);
                __threadfence();
                g_h2gen = h2base + 1u;
            }
        }
    } else {
        // fire-and-forget prefetch of the resident dec region, then wait
        pf_resident_all(dW2);
    }

    // ===== wait for h2 (single spinner per block) =====
    if (tid == 0) {
        while (g_h2gen == h2base) { }
        __threadfence();
    }
    __syncthreads();

    // ===== Stage 6: out = dec_W2 @ h2 + db2 (131072 x 450) =====
    {
        for (int i = tid; i < 900; i += NTHR)
            sh[i] = __ldcg(&g_h2[(i < 450) ? i : (i - 450)]);
        __syncthreads();
        const float4* VV = reinterpret_cast<const float4*>(sh);
        const int gw = blk * 32 + wid;
        const bool lo16 = (lane < 16);

        int pr = gw;
        // resident half: evict-normal -> stays in L2 across graph replays
        for (; pr < PR_RES; pr += NWARPS) {
            const float4* wr = reinterpret_cast<const float4*>(dW2 + (size_t)pr * 900);
            float acc0, acc1;
            dec_pair<false>(wr, VV, lane, acc0, acc1);
            float z = lo16 ? acc0 : acc1;
            z += __shfl_xor_sync(0xFFFFFFFFu, lo16 ? acc1 : acc0, 16);
            #pragma unroll
            for (int o = 8; o; o >>= 1) z += __shfl_xor_sync(0xFFFFFFFFu, z, o);
            if (lane == 0)  out[2 * pr]     = z + __ldg(db2 + 2 * pr);
            if (lane == 16) out[2 * pr + 1] = z + __ldg(db2 + 2 * pr + 1);
        }
        // streaming half: evict-first
        for (; pr < NPAIRS; pr += NWARPS) {
            const float4* wr = reinterpret_cast<const float4*>(dW2 + (size_t)pr * 900);
            float acc0, acc1;
            dec_pair<true>(wr, VV, lane, acc0, acc1);
            float z = lo16 ? acc0 : acc1;
            z += __shfl_xor_sync(0xFFFFFFFFu, lo16 ? acc1 : acc0, 16);
            #pragma unroll
            for (int o = 8; o; o >>= 1) z += __shfl_xor_sync(0xFFFFFFFFu, z, o);
            if (lane == 0)  out[2 * pr]     = z + __ldg(db2 + 2 * pr);
            if (lane == 16) out[2 * pr + 1] = z + __ldg(db2 + 2 * pr + 1);
        }
    }
}

// ---------------------------------------------------------------------------
// Inputs: x, t, TwE, PE, CE, mE, ext_W1, ext_b1, ext_W2, ext_b2,
//         dec_W1, dec_b1, dec_W2, dec_b2
// ---------------------------------------------------------------------------
extern "C" void kernel_launch(void* const* d_in, const int* in_sizes, int n_in,
                              void* d_out, int out_size)
{
    const float* x   = (const float*)d_in[0];
    const float* TwE = (const float*)d_in[2];
    const float* PE  = (const float*)d_in[3];
    const float* CE  = (const float*)d_in[4];
    const float* mE  = (const float*)d_in[5];
    const float* eW1 = (const float*)d_in[6];
    const float* eb1 = (const float*)d_in[7];
    const float* eW2 = (const float*)d_in[8];
    const float* eb2 = (const float*)d_in[9];
    const float* dW1 = (const float*)d_in[10];
    const float* db1 = (const float*)d_in[11];
    const float* dW2 = (const float*)d_in[12];
    const float* db2 = (const float*)d_in[13];
    float* out = (float*)d_out;

    const int xoff = in_sizes[0] - 4 * 256 * 128;

    fused_kernel<<<NBLK, NTHR>>>(x, TwE, PE, CE, mE,
                                 eW1, eb1, eW2, eb2,
                                 dW1, db1, dW2, db2,
                                 out, xoff);
    (void)n_in; (void)out_size;
}